// round 5
// baseline (speedup 1.0000x reference)
#include <cuda_runtime.h>

// Problem constants (fixed by the reference setup)
#define LSEQ   768
#define BATCH  2
#define N_MSA  4
#define DM     128
#define NREL   63   // 2*MAX_LEN - 1

// ---------------------------------------------------------------------------
// Single fused kernel: one block per (b, i).
// Prologue (per block, ~1-2 us): compute
//   P[t][d] = masked_emb[t] @ W_proj[:64, d]
//   Q[t][d] = masked_emb[t] @ W_proj[64:, d]
// then fold into three fused tables (si = seq[i], bias = b_proj + b_pos):
//   s_lo [t] = P[si] + Q[t] + bias + W_pos[62]   (j <= i-31, rel saturated)
//   s_hi [t] = P[si] + Q[t] + bias + W_pos[0]    (j >= i+31, rel saturated)
//   s_mid[t] = P[si] + Q[t] + bias               (+ W_pos[rel] from L2)
// Main loop: 768 coalesced 512B/warp stores, plain write-back policy.
// ---------------------------------------------------------------------------
__global__ __launch_bounds__(256, 8) void pair_kernel(const int*   __restrict__ msa,
                                                      const float* __restrict__ emb,
                                                      const float* __restrict__ W_proj,
                                                      const float* __restrict__ b_proj,
                                                      const float* __restrict__ W_pos,
                                                      const float* __restrict__ b_pos,
                                                      float* __restrict__ out) {
    __shared__ unsigned char s_seq[LSEQ];
    __shared__ float  s_emb[5 * 64];
    __shared__ float  s_P[5 * DM];
    __shared__ float  s_Q[5 * DM];
    __shared__ float4 s_lo [5 * 32];
    __shared__ float4 s_mid[5 * 32];
    __shared__ float4 s_hi [5 * 32];

    int tid  = threadIdx.x;
    int lane = tid & 31;
    int warp = tid >> 5;

    int bx = blockIdx.x;                 // b*LSEQ + i
    int b  = (bx >= LSEQ) ? 1 : 0;
    int i  = bx - b * LSEQ;

    // Load this batch's sequence (row 0 of the MSA) + the tiny emb table
    const int* seq = msa + (size_t)b * N_MSA * LSEQ;
    for (int k = tid; k < LSEQ; k += 256) s_seq[k] = (unsigned char)seq[k];
    for (int k = tid; k < 5 * 64; k += 256) s_emb[k] = emb[k];
    __syncthreads();

    // P/Q tables: thread d accumulates all 4 nonzero tokens over k
    if (tid < DM) {
        int d = tid;
        float p1 = 0.f, p2 = 0.f, p3 = 0.f, p4 = 0.f;
        float q1 = 0.f, q2 = 0.f, q3 = 0.f, q4 = 0.f;
        #pragma unroll 8
        for (int k = 0; k < 64; k++) {
            float wt = W_proj[k * DM + d];
            float wb = W_proj[(64 + k) * DM + d];
            float e1 = s_emb[ 64 + k], e2 = s_emb[128 + k];
            float e3 = s_emb[192 + k], e4 = s_emb[256 + k];
            p1 = fmaf(e1, wt, p1);  q1 = fmaf(e1, wb, q1);
            p2 = fmaf(e2, wt, p2);  q2 = fmaf(e2, wb, q2);
            p3 = fmaf(e3, wt, p3);  q3 = fmaf(e3, wb, q3);
            p4 = fmaf(e4, wt, p4);  q4 = fmaf(e4, wb, q4);
        }
        s_P[0 * DM + d] = 0.f;  s_Q[0 * DM + d] = 0.f;   // token 0 masked
        s_P[1 * DM + d] = p1;   s_Q[1 * DM + d] = q1;
        s_P[2 * DM + d] = p2;   s_Q[2 * DM + d] = q2;
        s_P[3 * DM + d] = p3;   s_Q[3 * DM + d] = q3;
        s_P[4 * DM + d] = p4;   s_Q[4 * DM + d] = q4;
    }
    __syncthreads();

    int si = s_seq[i];

    // Fused tables (160 threads: t = tid>>5, lane covers d as float4)
    if (tid < 5 * 32) {
        int t = tid >> 5;
        float4 p   = ((const float4*)s_P)[si * 32 + lane];
        float4 q   = ((const float4*)s_Q)[t  * 32 + lane];
        float4 bp  = ((const float4*)b_proj)[lane];
        float4 bps = ((const float4*)b_pos )[lane];
        float4 w0  = ((const float4*)W_pos)[ 0 * 32 + lane];
        float4 w62 = ((const float4*)W_pos)[62 * 32 + lane];
        float4 c = make_float4(p.x + q.x + bp.x + bps.x,
                               p.y + q.y + bp.y + bps.y,
                               p.z + q.z + bp.z + bps.z,
                               p.w + q.w + bp.w + bps.w);
        s_mid[tid] = c;
        s_lo [tid] = make_float4(c.x + w62.x, c.y + w62.y, c.z + w62.z, c.w + w62.w);
        s_hi [tid] = make_float4(c.x + w0.x,  c.y + w0.y,  c.z + w0.z,  c.w + w0.w);
    }
    __syncthreads();

    float4* outp = (float4*)out + (size_t)bx * LSEQ * 32;
    const float4* Wp4 = (const float4*)W_pos;

    int jloEnd = i - 30;   // j < jloEnd  -> rel = 62
    int jhiBeg = i + 31;   // j >= jhiBeg -> rel = 0

    #pragma unroll 4
    for (int j = warp; j < LSEQ; j += 8) {
        int sj = s_seq[j];                      // warp-uniform broadcast
        float4 v;
        if (j < jloEnd) {                       // warp-uniform branch
            v = s_lo[sj * 32 + lane];
        } else if (j >= jhiBeg) {
            v = s_hi[sj * 32 + lane];
        } else {
            float4 c = s_mid[sj * 32 + lane];
            float4 r = __ldg(&Wp4[(i - j + 31) * 32 + lane]);
            v = make_float4(c.x + r.x, c.y + r.y, c.z + r.z, c.w + r.w);
        }
        outp[(size_t)j * 32 + lane] = v;        // plain write-back store
    }
}

extern "C" void kernel_launch(void* const* d_in, const int* in_sizes, int n_in,
                              void* d_out, int out_size) {
    const int*   msa    = (const int*)  d_in[0];  // msa_tokens (B, N_MSA, L) int32
    const float* emb    = (const float*)d_in[1];  // (5, 64)
    const float* W_proj = (const float*)d_in[2];  // (128, 128)
    const float* b_proj = (const float*)d_in[3];  // (128,)
    const float* W_pos  = (const float*)d_in[4];  // (63, 128)
    const float* b_pos  = (const float*)d_in[5];  // (128,)
    float* out = (float*)d_out;                   // (B, L, L, 128) fp32

    pair_kernel<<<BATCH * LSEQ, 256>>>(msa, emb, W_proj, b_proj, W_pos, b_pos, out);
}

// round 6
// speedup vs baseline: 1.4246x; 1.4246x over previous
#include <cuda_runtime.h>

// Problem constants (fixed by the reference setup)
#define LSEQ   768
#define BATCH  2
#define N_MSA  4
#define DM     128
#define NREL   63   // 2*MAX_LEN - 1

// Scratch tables (device globals — no allocation allowed)
__device__ float g_Ptab[5][DM];   // masked_emb[t] @ W_proj[:64, :]
__device__ float g_Qtab[5][DM];   // masked_emb[t] @ W_proj[64:, :]
__device__ float g_R[NREL][DM];   // W_pos[r] + b_proj + b_pos

// ---------------------------------------------------------------------------
// Table setup: 68 tiny blocks. Blocks 0..4 -> Ptab/Qtab row t,
// blocks 5..67 -> R row (blockIdx-5).
// ---------------------------------------------------------------------------
__global__ void setup_kernel(const float* __restrict__ emb,
                             const float* __restrict__ W_proj,
                             const float* __restrict__ b_proj,
                             const float* __restrict__ W_pos,
                             const float* __restrict__ b_pos) {
    int d = threadIdx.x;          // 0..127
    int task = blockIdx.x;
    if (task < 5) {
        int t = task;
        float pt = 0.f, qt = 0.f;
        if (t != 0) {             // token 0 is masked to zero
            #pragma unroll 16
            for (int k = 0; k < 64; k++) {
                float ek = emb[t * 64 + k];
                pt = fmaf(ek, W_proj[k * DM + d], pt);
                qt = fmaf(ek, W_proj[(64 + k) * DM + d], qt);
            }
        }
        g_Ptab[t][d] = pt;
        g_Qtab[t][d] = qt;
    } else {
        int r = task - 5;
        g_R[r][d] = W_pos[r * DM + d] + b_proj[d] + b_pos[d];
    }
}

// Select one of 5 float4 table entries by token id (0..4) with FSEL chains.
// sj is warp-uniform; branch-free keeps the store stream dense.
__device__ __forceinline__ float4 sel5(int sj, float4 t0, float4 t1, float4 t2,
                                       float4 t3, float4 t4) {
    bool a = (sj < 2), b0 = (sj == 0), c2 = (sj == 2), c3 = (sj == 3);
    float4 v;
    v.x = a ? (b0 ? t0.x : t1.x) : (c2 ? t2.x : (c3 ? t3.x : t4.x));
    v.y = a ? (b0 ? t0.y : t1.y) : (c2 ? t2.y : (c3 ? t3.y : t4.y));
    v.z = a ? (b0 ? t0.z : t1.z) : (c2 ? t2.z : (c3 ? t3.z : t4.z));
    v.w = a ? (b0 ? t0.w : t1.w) : (c2 ? t2.w : (c3 ? t3.w : t4.w));
    return v;
}

// Hot loop for a saturated-rel region: table lives entirely in registers.
// Per row: 1x LDS.U8 (token) + ~20 FSEL/ISETP + 1x STG.128 — no table LDS.
__device__ __forceinline__ void run_reg(int jb, int je, const float4* __restrict__ tab,
                                        const unsigned char* __restrict__ s_seq,
                                        float4* __restrict__ outp, int lane) {
    if (jb >= je) return;
    float4 t0 = tab[0 * 32 + lane];
    float4 t1 = tab[1 * 32 + lane];
    float4 t2 = tab[2 * 32 + lane];
    float4 t3 = tab[3 * 32 + lane];
    float4 t4 = tab[4 * 32 + lane];
    #pragma unroll 4
    for (int j = jb; j < je; ++j) {
        int sj = s_seq[j];                               // warp-uniform broadcast
        float4 v = sel5(sj, t0, t1, t2, t3, t4);
        __stcs(&outp[(size_t)j * 32 + lane], v);
    }
}

// ---------------------------------------------------------------------------
// Main kernel: one block per (b, i). Each warp owns a CONTIGUOUS 96-row
// j-chunk, split into three rel-regions:
//   j <= i-31 : reg table s_lo  (Ptab[si]+Qtab[t]+R[62])
//   j >= i+31 : reg table s_hi  (Ptab[si]+Qtab[t]+R[0])
//   else      : smem s_mid + R[i-j+31] from L2 (<=61 rows per block)
// ---------------------------------------------------------------------------
__global__ __launch_bounds__(256, 6) void pair_kernel(const int* __restrict__ msa,
                                                      float* __restrict__ out) {
    __shared__ unsigned char s_seq[LSEQ];
    __shared__ float4 s_lo [5 * 32];
    __shared__ float4 s_mid[5 * 32];
    __shared__ float4 s_hi [5 * 32];

    int bx  = blockIdx.x;               // b*LSEQ + i
    int b   = (bx >= LSEQ) ? 1 : 0;
    int i   = bx - b * LSEQ;
    int tid = threadIdx.x;
    int lane = tid & 31;
    int warp = tid >> 5;

    // Load this batch's sequence (row 0 of the MSA) into shared as bytes
    const int* seq = msa + (size_t)b * N_MSA * LSEQ;
    for (int k = tid; k < LSEQ; k += 256) s_seq[k] = (unsigned char)seq[k];
    __syncthreads();

    int si = s_seq[i];

    // Build fused tables (160 threads: t = tid>>5, lane covers d as float4)
    if (tid < 5 * 32) {
        int t = tid >> 5;
        float4 p   = ((const float4*)g_Ptab)[si * 32 + lane];
        float4 q   = ((const float4*)g_Qtab)[t  * 32 + lane];
        float4 r0  = ((const float4*)g_R)[ 0 * 32 + lane];
        float4 r62 = ((const float4*)g_R)[62 * 32 + lane];
        float4 c = make_float4(p.x + q.x, p.y + q.y, p.z + q.z, p.w + q.w);
        s_mid[tid] = c;
        s_lo [tid] = make_float4(c.x + r62.x, c.y + r62.y, c.z + r62.z, c.w + r62.w);
        s_hi [tid] = make_float4(c.x + r0.x,  c.y + r0.y,  c.z + r0.z,  c.w + r0.w);
    }
    __syncthreads();

    float4* outp = (float4*)out + (size_t)bx * LSEQ * 32;
    const float4* gR4 = (const float4*)g_R;

    // This warp's contiguous chunk and its region boundaries
    int chunkBeg = warp * (LSEQ / 8);
    int chunkEnd = chunkBeg + (LSEQ / 8);
    int loEnd  = min(max(i - 30, chunkBeg), chunkEnd);   // rows with rel=62
    int midEnd = min(max(i + 31, chunkBeg), chunkEnd);   // rows with rel in (0,62)

    // lo region: register table
    run_reg(chunkBeg, loEnd, s_lo, s_seq, outp, lane);

    // mid region (<=61 rows total per block): smem table + W_pos row from L2
    for (int j = loEnd; j < midEnd; ++j) {
        int sj = s_seq[j];
        float4 c = s_mid[sj * 32 + lane];
        float4 r = __ldg(&gR4[(i - j + 31) * 32 + lane]);
        float4 v = make_float4(c.x + r.x, c.y + r.y, c.z + r.z, c.w + r.w);
        __stcs(&outp[(size_t)j * 32 + lane], v);
    }

    // hi region: register table
    run_reg(midEnd, chunkEnd, s_hi, s_seq, outp, lane);
}

extern "C" void kernel_launch(void* const* d_in, const int* in_sizes, int n_in,
                              void* d_out, int out_size) {
    const int*   msa    = (const int*)  d_in[0];  // msa_tokens (B, N_MSA, L) int32
    const float* emb    = (const float*)d_in[1];  // (5, 64)
    const float* W_proj = (const float*)d_in[2];  // (128, 128)
    const float* b_proj = (const float*)d_in[3];  // (128,)
    const float* W_pos  = (const float*)d_in[4];  // (63, 128)
    const float* b_pos  = (const float*)d_in[5];  // (128,)
    float* out = (float*)d_out;                   // (B, L, L, 128) fp32

    setup_kernel<<<5 + NREL, DM>>>(emb, W_proj, b_proj, W_pos, b_pos);
    pair_kernel<<<BATCH * LSEQ, 256>>>(msa, out);
}